// round 9
// baseline (speedup 1.0000x reference)
#include <cuda_runtime.h>
#include <cuda_bf16.h>
#include <cstdint>

// Problem constants (fixed by the dataset)
#define N_NODES_MAX 50048
#define N_EDGES_MAX 800000
#define IN_FEATS    128
#define NUM_HEADS   4
#define OUT_FEATS   32
#define HD          (NUM_HEADS * OUT_FEATS)   // 128

#define SCAN_B 1024
#define MAX_BLOCKS ((N_NODES_MAX + SCAN_B - 1) / SCAN_B + 2)

// Scratch (static __device__ arrays; no allocation allowed)
__device__ float g_ft[N_NODES_MAX * HD];     // projected features [N,128]
__device__ int   g_cnt[N_NODES_MAX];         // in-degree histogram
__device__ int   g_off[N_NODES_MAX];         // CSR row starts
__device__ int   g_cur[N_NODES_MAX];         // scatter cursors
__device__ int   g_bsum[MAX_BLOCKS];         // per-block sums for scan
__device__ int   g_csr_src[N_EDGES_MAX];     // src node per CSR slot

// ---------------------------------------------------------------------------
// K1: in-degree histogram
// ---------------------------------------------------------------------------
__global__ void hist_kernel(const int* __restrict__ dst, int E) {
    int i = blockIdx.x * blockDim.x + threadIdx.x;
    if (i < E) atomicAdd(&g_cnt[dst[i]], 1);
}

// ---------------------------------------------------------------------------
// K2a: per-block sums for the scan
// ---------------------------------------------------------------------------
__global__ void scan_phase1(int N) {
    int i = blockIdx.x * SCAN_B + threadIdx.x;
    int v = (i < N) ? g_cnt[i] : 0;
    #pragma unroll
    for (int o = 16; o > 0; o >>= 1) v += __shfl_xor_sync(0xffffffffu, v, o);
    __shared__ int wsum[32];
    int lane = threadIdx.x & 31, w = threadIdx.x >> 5;
    if (lane == 0) wsum[w] = v;
    __syncthreads();
    if (w == 0) {
        int x = wsum[lane];
        #pragma unroll
        for (int o = 16; o > 0; o >>= 1) x += __shfl_xor_sync(0xffffffffu, x, o);
        if (lane == 0) g_bsum[blockIdx.x] = x;
    }
}

// ---------------------------------------------------------------------------
// K2b: per-block scan with inter-block base folded in (warp 0 sums g_bsum).
// ---------------------------------------------------------------------------
__global__ void scan_phase3(int N) {
    __shared__ int base_off;
    int lane = threadIdx.x & 31, w = threadIdx.x >> 5;
    if (threadIdx.x < 32) {
        int acc = 0;
        for (int j = lane; j < (int)blockIdx.x; j += 32) acc += g_bsum[j];
        #pragma unroll
        for (int o = 16; o > 0; o >>= 1) acc += __shfl_xor_sync(0xffffffffu, acc, o);
        if (lane == 0) base_off = acc;
    }
    int i = blockIdx.x * SCAN_B + threadIdx.x;
    int v = (i < N) ? g_cnt[i] : 0;
    int x = v;
    #pragma unroll
    for (int o = 1; o < 32; o <<= 1) {
        int y = __shfl_up_sync(0xffffffffu, x, o);
        if (lane >= o) x += y;
    }
    __shared__ int woff[32];
    if (lane == 31) woff[w] = x;
    __syncthreads();
    if (w == 0) {
        int y = woff[lane];
        int z = y;
        #pragma unroll
        for (int o = 1; o < 32; o <<= 1) {
            int t2 = __shfl_up_sync(0xffffffffu, z, o);
            if (lane >= o) z += t2;
        }
        woff[lane] = z - y;
    }
    __syncthreads();
    int excl = (x - v) + woff[w] + base_off;
    if (i < N) { g_off[i] = excl; g_cur[i] = excl; }
}

// ---------------------------------------------------------------------------
// K3: scatter src ids into CSR slots
// ---------------------------------------------------------------------------
__global__ void scatter_kernel(const int* __restrict__ src,
                               const int* __restrict__ dst, int E) {
    int i = blockIdx.x * blockDim.x + threadIdx.x;
    if (i < E) {
        int pos = atomicAdd(&g_cur[dst[i]], 1);
        g_csr_src[pos] = src[i];
    }
}

// ---------------------------------------------------------------------------
// K4: projection GEMM, FFMA2 with PRE-SPLATTED A in SMEM.
// 128x128 tile, BK=16, 256 threads, 8x8 microtile as 8x4 f32x2 pairs.
// As2[k][r] holds {v,v} (u64) so the inner loop is pure LDS + fma.rn.f32x2
// (no ALU packing on the critical path). Per k: 2 LDS.128 + 8 LDS.64 +
// 32 FFMA2 (vs 64 FFMA) -> FMA-pipe time halves.
// Register-staged prefetch of k-block t+1 over compute of t.
// Runs on a forked stream, concurrent with the CSR build.
// ---------------------------------------------------------------------------
#define GM 128
#define GK 16
__global__ void __launch_bounds__(256, 2)
gemm_kernel(const float* __restrict__ feat,
            const float* __restrict__ W,
            int N) {
    __shared__ unsigned long long As2[GK][GM];  // splat pairs {v,v}: 16KB
    __shared__ float Bs[GK][HD];                // W tile, transposed: 8KB

    const int tid = threadIdx.x;           // 0..255
    const int tx  = tid & 15;              // col group: cols tx*8..tx*8+7
    const int ty  = tid >> 4;              // row group: rows ty*8..ty*8+7
    const int row0 = blockIdx.x * GM;

    const int rA0 = (tid + 0)   >> 2, kq0 = (tid + 0)   & 3;
    const int rA1 = (tid + 256) >> 2, kq1 = (tid + 256) & 3;

    unsigned long long acc[8][4];   // 8 rows x 4 f32x2 pairs (= 8 cols)
    #pragma unroll
    for (int i = 0; i < 8; i++)
        #pragma unroll
        for (int j = 0; j < 4; j++) acc[i][j] = 0ULL;

    // Prologue: stage k-block 0 into registers
    float4 fa0, fa1, fw0, fw1;
    {
        fa0 = make_float4(0.f, 0.f, 0.f, 0.f);
        fa1 = fa0;
        if (row0 + rA0 < N) fa0 = *(const float4*)&feat[(size_t)(row0 + rA0) * IN_FEATS + (kq0 << 2)];
        if (row0 + rA1 < N) fa1 = *(const float4*)&feat[(size_t)(row0 + rA1) * IN_FEATS + (kq1 << 2)];
        fw0 = *(const float4*)&W[(size_t)rA0 * IN_FEATS + (kq0 << 2)];
        fw1 = *(const float4*)&W[(size_t)rA1 * IN_FEATS + (kq1 << 2)];
    }

    #pragma unroll 1
    for (int kb = 0; kb < IN_FEATS / GK; kb++) {
        // Commit staged registers to shared: A splatted to u64 pairs, B plain.
        {
            unsigned long long s;
            asm("mov.b64 %0, {%1, %1};" : "=l"(s) : "f"(fa0.x)); As2[(kq0 << 2) + 0][rA0] = s;
            asm("mov.b64 %0, {%1, %1};" : "=l"(s) : "f"(fa0.y)); As2[(kq0 << 2) + 1][rA0] = s;
            asm("mov.b64 %0, {%1, %1};" : "=l"(s) : "f"(fa0.z)); As2[(kq0 << 2) + 2][rA0] = s;
            asm("mov.b64 %0, {%1, %1};" : "=l"(s) : "f"(fa0.w)); As2[(kq0 << 2) + 3][rA0] = s;
            asm("mov.b64 %0, {%1, %1};" : "=l"(s) : "f"(fa1.x)); As2[(kq1 << 2) + 0][rA1] = s;
            asm("mov.b64 %0, {%1, %1};" : "=l"(s) : "f"(fa1.y)); As2[(kq1 << 2) + 1][rA1] = s;
            asm("mov.b64 %0, {%1, %1};" : "=l"(s) : "f"(fa1.z)); As2[(kq1 << 2) + 2][rA1] = s;
            asm("mov.b64 %0, {%1, %1};" : "=l"(s) : "f"(fa1.w)); As2[(kq1 << 2) + 3][rA1] = s;
        }
        Bs[(kq0 << 2) + 0][rA0] = fw0.x; Bs[(kq0 << 2) + 1][rA0] = fw0.y;
        Bs[(kq0 << 2) + 2][rA0] = fw0.z; Bs[(kq0 << 2) + 3][rA0] = fw0.w;
        Bs[(kq1 << 2) + 0][rA1] = fw1.x; Bs[(kq1 << 2) + 1][rA1] = fw1.y;
        Bs[(kq1 << 2) + 2][rA1] = fw1.z; Bs[(kq1 << 2) + 3][rA1] = fw1.w;
        __syncthreads();

        // Stage next k-block (LDG latency overlaps the FFMA2 block below)
        if (kb + 1 < IN_FEATS / GK) {
            int kc = (kb + 1) * GK;
            fa0 = make_float4(0.f, 0.f, 0.f, 0.f);
            fa1 = fa0;
            if (row0 + rA0 < N) fa0 = *(const float4*)&feat[(size_t)(row0 + rA0) * IN_FEATS + kc + (kq0 << 2)];
            if (row0 + rA1 < N) fa1 = *(const float4*)&feat[(size_t)(row0 + rA1) * IN_FEATS + kc + (kq1 << 2)];
            fw0 = *(const float4*)&W[(size_t)rA0 * IN_FEATS + kc + (kq0 << 2)];
            fw1 = *(const float4*)&W[(size_t)rA1 * IN_FEATS + kc + (kq1 << 2)];
        }

        #pragma unroll
        for (int k = 0; k < GK; k++) {
            float4 b0 = *(const float4*)&Bs[k][(tx << 3) + 0];
            float4 b1 = *(const float4*)&Bs[k][(tx << 3) + 4];
            unsigned long long bp[4];
            asm("mov.b64 %0, {%1, %2};" : "=l"(bp[0]) : "f"(b0.x), "f"(b0.y));
            asm("mov.b64 %0, {%1, %2};" : "=l"(bp[1]) : "f"(b0.z), "f"(b0.w));
            asm("mov.b64 %0, {%1, %2};" : "=l"(bp[2]) : "f"(b1.x), "f"(b1.y));
            asm("mov.b64 %0, {%1, %2};" : "=l"(bp[3]) : "f"(b1.z), "f"(b1.w));
            #pragma unroll
            for (int i = 0; i < 8; i++) {
                unsigned long long ap = As2[k][(ty << 3) + i];   // LDS.64 splat
                #pragma unroll
                for (int jp = 0; jp < 4; jp++)
                    asm("fma.rn.f32x2 %0, %1, %2, %0;"
                        : "+l"(acc[i][jp]) : "l"(ap), "l"(bp[jp]));
            }
        }
        __syncthreads();
    }

    // Epilogue: each row's 4 u64 pairs == 8 contiguous floats; two STG.128.
    #pragma unroll
    for (int i = 0; i < 8; i++) {
        int r = row0 + (ty << 3) + i;
        if (r < N) {
            unsigned long long* d =
                (unsigned long long*)&g_ft[(size_t)r * HD + (tx << 3)];
            ulonglong2 v0; v0.x = acc[i][0]; v0.y = acc[i][1];
            ulonglong2 v1; v1.x = acc[i][2]; v1.y = acc[i][3];
            *(ulonglong2*)(d + 0) = v0;
            *(ulonglong2*)(d + 2) = v1;
        }
    }
}

// ---------------------------------------------------------------------------
// K5: atomic-free aggregation. One warp per DST node, prefetch depth 2:
// gathers for edges t+1 and t+2 are in flight while edge t computes,
// lifting per-warp MLP to ~3 to saturate the LTS gather bandwidth.
// ft[dst] held in registers (1 float4/lane). No atomics anywhere.
// Max-subtraction skipped: mathematically identical softmax; |p*scale| <~ 7.
// ---------------------------------------------------------------------------
__global__ void agg_kernel(float* __restrict__ out, int N) {
    const int node = (blockIdx.x * blockDim.x + threadIdx.x) >> 5;
    if (node >= N) return;
    const int lane = threadIdx.x & 31;

    const int start = g_off[node];
    const int deg   = g_cnt[node];

    const float4* ft4 = (const float4*)g_ft;
    const float4 b4 = ft4[(size_t)node * 32 + lane];

    float4 acc = make_float4(0.f, 0.f, 0.f, 0.f);
    float s = 0.0f;
    const float scale = 0.17677669529663687f;  // 1/sqrt(32)

    for (int base = 0; base < deg; base += 32) {
        int j = base + lane;
        int sj = (j < deg) ? g_csr_src[start + j] : 0;
        int cnt = min(32, deg - base);

        // prologue: two gathers in flight
        float4 a_t, a_t1;
        {
            int sn0 = __shfl_sync(0xffffffffu, sj, 0);
            a_t = ft4[(size_t)sn0 * 32 + lane];
        }
        if (cnt > 1) {
            int sn1 = __shfl_sync(0xffffffffu, sj, 1);
            a_t1 = ft4[(size_t)sn1 * 32 + lane];
        }

        #pragma unroll 2
        for (int t = 0; t < cnt; t++) {
            float4 cur = a_t;
            a_t = a_t1;
            if (t + 2 < cnt) {   // keep 2 gathers outstanding
                int sn = __shfl_sync(0xffffffffu, sj, t + 2);
                a_t1 = ft4[(size_t)sn * 32 + lane];
            }
            float p = cur.x * b4.x + cur.y * b4.y + cur.z * b4.z + cur.w * b4.w;
            p += __shfl_xor_sync(0xffffffffu, p, 4);
            p += __shfl_xor_sync(0xffffffffu, p, 2);
            p += __shfl_xor_sync(0xffffffffu, p, 1);
            float e = __expf(p * scale);
            s += e;
            acc.x += e * cur.x; acc.y += e * cur.y;
            acc.z += e * cur.z; acc.w += e * cur.w;
        }
    }

    float inv = (deg > 0) ? (1.0f / s) : 0.0f;
    float4 r = make_float4(acc.x * inv, acc.y * inv, acc.z * inv, acc.w * inv);
    ((float4*)out)[(size_t)node * 32 + lane] = r;
}

// ---------------------------------------------------------------------------
extern "C" void kernel_launch(void* const* d_in, const int* in_sizes, int n_in,
                              void* d_out, int out_size) {
    const float* feat = (const float*)d_in[0];
    const float* W    = (const float*)d_in[1];
    const int*   src  = (const int*)d_in[2];
    const int*   dst  = (const int*)d_in[3];
    float* out = (float*)d_out;

    const int N = in_sizes[0] / IN_FEATS;   // 50000
    const int E = in_sizes[2];              // 800000
    const int nb = (N + SCAN_B - 1) / SCAN_B;

    // One-time resources (stream/events/symbol addr) — resources only;
    // the captured work per call is identical every time.
    static cudaStream_t s_gemm = nullptr;
    static cudaEvent_t  ev_fork = nullptr, ev_join = nullptr;
    static int* cnt_ptr = nullptr;
    if (s_gemm == nullptr) {
        cudaStreamCreateWithFlags(&s_gemm, cudaStreamNonBlocking);
        cudaEventCreateWithFlags(&ev_fork, cudaEventDisableTiming);
        cudaEventCreateWithFlags(&ev_join, cudaEventDisableTiming);
        cudaGetSymbolAddress((void**)&cnt_ptr, g_cnt);
    }

    // Fork point recorded BEFORE any work: the GEMM branch depends on nothing
    // from the CSR chain even though it is issued after it (issue order only
    // changes which launch ncu's -s window catches).
    cudaEventRecord(ev_fork, 0);

    // ---- main stream: CSR build branch (depends only on src, dst) ----
    cudaMemsetAsync(cnt_ptr, 0, (size_t)N * sizeof(int));
    hist_kernel<<<(E + 255) / 256, 256>>>(dst, E);
    scan_phase1<<<nb, SCAN_B>>>(N);
    scan_phase3<<<nb, SCAN_B>>>(N);
    scatter_kernel<<<(E + 255) / 256, 256>>>(src, dst, E);

    // ---- side stream: GEMM branch (depends only on feat, W) ----
    cudaStreamWaitEvent(s_gemm, ev_fork, 0);
    gemm_kernel<<<(N + GM - 1) / GM, 256, 0, s_gemm>>>(feat, W, N);
    cudaEventRecord(ev_join, s_gemm);

    // ---- join, then aggregate ----
    cudaStreamWaitEvent(0, ev_join, 0);
    {
        int warps_per_block = 8;  // 256 threads
        int blocks = (N + warps_per_block - 1) / warps_per_block;
        agg_kernel<<<blocks, 256>>>(out, N);
    }
}

// round 10
// speedup vs baseline: 1.1019x; 1.1019x over previous
#include <cuda_runtime.h>
#include <cuda_bf16.h>
#include <cstdint>

// Problem constants (fixed by the dataset)
#define N_NODES_MAX 50048
#define N_EDGES_MAX 800000
#define IN_FEATS    128
#define NUM_HEADS   4
#define OUT_FEATS   32
#define HD          (NUM_HEADS * OUT_FEATS)   // 128

#define SCAN_B 1024
#define MAX_BLOCKS ((N_NODES_MAX + SCAN_B - 1) / SCAN_B + 2)

// Scratch (static __device__ arrays; no allocation allowed)
__device__ float g_ft[N_NODES_MAX * HD];     // projected features [N,128]
__device__ int   g_cnt[N_NODES_MAX];         // in-degree histogram
__device__ int   g_off[N_NODES_MAX];         // CSR row starts
__device__ int   g_cur[N_NODES_MAX];         // scatter cursors
__device__ int   g_bsum[MAX_BLOCKS];         // per-block sums for scan
__device__ int   g_csr_src[N_EDGES_MAX];     // src node per CSR slot

// ---------------------------------------------------------------------------
// K1: in-degree histogram
// ---------------------------------------------------------------------------
__global__ void hist_kernel(const int* __restrict__ dst, int E) {
    int i = blockIdx.x * blockDim.x + threadIdx.x;
    if (i < E) atomicAdd(&g_cnt[dst[i]], 1);
}

// ---------------------------------------------------------------------------
// K2a: per-block sums for the scan
// ---------------------------------------------------------------------------
__global__ void scan_phase1(int N) {
    int i = blockIdx.x * SCAN_B + threadIdx.x;
    int v = (i < N) ? g_cnt[i] : 0;
    #pragma unroll
    for (int o = 16; o > 0; o >>= 1) v += __shfl_xor_sync(0xffffffffu, v, o);
    __shared__ int wsum[32];
    int lane = threadIdx.x & 31, w = threadIdx.x >> 5;
    if (lane == 0) wsum[w] = v;
    __syncthreads();
    if (w == 0) {
        int x = wsum[lane];
        #pragma unroll
        for (int o = 16; o > 0; o >>= 1) x += __shfl_xor_sync(0xffffffffu, x, o);
        if (lane == 0) g_bsum[blockIdx.x] = x;
    }
}

// ---------------------------------------------------------------------------
// K2b: per-block scan with inter-block base folded in (warp 0 sums g_bsum).
// ---------------------------------------------------------------------------
__global__ void scan_phase3(int N) {
    __shared__ int base_off;
    int lane = threadIdx.x & 31, w = threadIdx.x >> 5;
    if (threadIdx.x < 32) {
        int acc = 0;
        for (int j = lane; j < (int)blockIdx.x; j += 32) acc += g_bsum[j];
        #pragma unroll
        for (int o = 16; o > 0; o >>= 1) acc += __shfl_xor_sync(0xffffffffu, acc, o);
        if (lane == 0) base_off = acc;
    }
    int i = blockIdx.x * SCAN_B + threadIdx.x;
    int v = (i < N) ? g_cnt[i] : 0;
    int x = v;
    #pragma unroll
    for (int o = 1; o < 32; o <<= 1) {
        int y = __shfl_up_sync(0xffffffffu, x, o);
        if (lane >= o) x += y;
    }
    __shared__ int woff[32];
    if (lane == 31) woff[w] = x;
    __syncthreads();
    if (w == 0) {
        int y = woff[lane];
        int z = y;
        #pragma unroll
        for (int o = 1; o < 32; o <<= 1) {
            int t2 = __shfl_up_sync(0xffffffffu, z, o);
            if (lane >= o) z += t2;
        }
        woff[lane] = z - y;
    }
    __syncthreads();
    int excl = (x - v) + woff[w] + base_off;
    if (i < N) { g_off[i] = excl; g_cur[i] = excl; }
}

// ---------------------------------------------------------------------------
// K3: scatter src ids into CSR slots
// ---------------------------------------------------------------------------
__global__ void scatter_kernel(const int* __restrict__ src,
                               const int* __restrict__ dst, int E) {
    int i = blockIdx.x * blockDim.x + threadIdx.x;
    if (i < E) {
        int pos = atomicAdd(&g_cur[dst[i]], 1);
        g_csr_src[pos] = src[i];
    }
}

// ---------------------------------------------------------------------------
// K4: projection GEMM with packed fp32 (FFMA2) — R8 version (measured best).
// 128x128 tile, BK=16, 256 threads, 8x8 microtile held as 8x4 f32x2 pairs.
// ---------------------------------------------------------------------------
#define GM 128
#define GK 16
__global__ void __launch_bounds__(256, 2)
gemm_kernel(const float* __restrict__ feat,
            const float* __restrict__ W,
            int N) {
    __shared__ float As[GK][GM];    // feat tile, transposed: As[k][r]   8KB
    __shared__ float Bs[GK][HD];    // W tile, transposed:    Bs[k][o]   8KB

    const int tid = threadIdx.x;           // 0..255
    const int tx  = tid & 15;              // col group: cols tx*8..tx*8+7
    const int ty  = tid >> 4;              // row group: rows ty*8..ty*8+7
    const int row0 = blockIdx.x * GM;

    const int rA0 = (tid + 0)   >> 2, kq0 = (tid + 0)   & 3;
    const int rA1 = (tid + 256) >> 2, kq1 = (tid + 256) & 3;

    unsigned long long acc[8][4];   // 8 rows x 4 f32x2 pairs (= 8 cols)
    #pragma unroll
    for (int i = 0; i < 8; i++)
        #pragma unroll
        for (int j = 0; j < 4; j++) acc[i][j] = 0ULL;

    // Prologue: stage k-block 0 into registers
    float4 fa0, fa1, fw0, fw1;
    {
        fa0 = make_float4(0.f, 0.f, 0.f, 0.f);
        fa1 = fa0;
        if (row0 + rA0 < N) fa0 = *(const float4*)&feat[(size_t)(row0 + rA0) * IN_FEATS + (kq0 << 2)];
        if (row0 + rA1 < N) fa1 = *(const float4*)&feat[(size_t)(row0 + rA1) * IN_FEATS + (kq1 << 2)];
        fw0 = *(const float4*)&W[(size_t)rA0 * IN_FEATS + (kq0 << 2)];
        fw1 = *(const float4*)&W[(size_t)rA1 * IN_FEATS + (kq1 << 2)];
    }

    #pragma unroll 1
    for (int kb = 0; kb < IN_FEATS / GK; kb++) {
        As[(kq0 << 2) + 0][rA0] = fa0.x; As[(kq0 << 2) + 1][rA0] = fa0.y;
        As[(kq0 << 2) + 2][rA0] = fa0.z; As[(kq0 << 2) + 3][rA0] = fa0.w;
        As[(kq1 << 2) + 0][rA1] = fa1.x; As[(kq1 << 2) + 1][rA1] = fa1.y;
        As[(kq1 << 2) + 2][rA1] = fa1.z; As[(kq1 << 2) + 3][rA1] = fa1.w;
        Bs[(kq0 << 2) + 0][rA0] = fw0.x; Bs[(kq0 << 2) + 1][rA0] = fw0.y;
        Bs[(kq0 << 2) + 2][rA0] = fw0.z; Bs[(kq0 << 2) + 3][rA0] = fw0.w;
        Bs[(kq1 << 2) + 0][rA1] = fw1.x; Bs[(kq1 << 2) + 1][rA1] = fw1.y;
        Bs[(kq1 << 2) + 2][rA1] = fw1.z; Bs[(kq1 << 2) + 3][rA1] = fw1.w;
        __syncthreads();

        if (kb + 1 < IN_FEATS / GK) {
            int kc = (kb + 1) * GK;
            fa0 = make_float4(0.f, 0.f, 0.f, 0.f);
            fa1 = fa0;
            if (row0 + rA0 < N) fa0 = *(const float4*)&feat[(size_t)(row0 + rA0) * IN_FEATS + kc + (kq0 << 2)];
            if (row0 + rA1 < N) fa1 = *(const float4*)&feat[(size_t)(row0 + rA1) * IN_FEATS + kc + (kq1 << 2)];
            fw0 = *(const float4*)&W[(size_t)rA0 * IN_FEATS + kc + (kq0 << 2)];
            fw1 = *(const float4*)&W[(size_t)rA1 * IN_FEATS + kc + (kq1 << 2)];
        }

        #pragma unroll
        for (int k = 0; k < GK; k++) {
            float4 a0 = *(const float4*)&As[k][(ty << 3) + 0];
            float4 a1 = *(const float4*)&As[k][(ty << 3) + 4];
            float4 b0 = *(const float4*)&Bs[k][(tx << 3) + 0];
            float4 b1 = *(const float4*)&Bs[k][(tx << 3) + 4];
            unsigned long long bp[4];
            asm("mov.b64 %0, {%1, %2};" : "=l"(bp[0]) : "f"(b0.x), "f"(b0.y));
            asm("mov.b64 %0, {%1, %2};" : "=l"(bp[1]) : "f"(b0.z), "f"(b0.w));
            asm("mov.b64 %0, {%1, %2};" : "=l"(bp[2]) : "f"(b1.x), "f"(b1.y));
            asm("mov.b64 %0, {%1, %2};" : "=l"(bp[3]) : "f"(b1.z), "f"(b1.w));
            float av[8] = {a0.x, a0.y, a0.z, a0.w, a1.x, a1.y, a1.z, a1.w};
            #pragma unroll
            for (int i = 0; i < 8; i++) {
                unsigned long long ap;
                asm("mov.b64 %0, {%1, %1};" : "=l"(ap) : "f"(av[i]));
                #pragma unroll
                for (int jp = 0; jp < 4; jp++)
                    asm("fma.rn.f32x2 %0, %1, %2, %0;"
                        : "+l"(acc[i][jp]) : "l"(ap), "l"(bp[jp]));
            }
        }
        __syncthreads();
    }

    #pragma unroll
    for (int i = 0; i < 8; i++) {
        int r = row0 + (ty << 3) + i;
        if (r < N) {
            unsigned long long* d =
                (unsigned long long*)&g_ft[(size_t)r * HD + (tx << 3)];
            ulonglong2 v0; v0.x = acc[i][0]; v0.y = acc[i][1];
            ulonglong2 v1; v1.x = acc[i][2]; v1.y = acc[i][3];
            *(ulonglong2*)(d + 0) = v0;
            *(ulonglong2*)(d + 2) = v1;
        }
    }
}

// ---------------------------------------------------------------------------
// K5: atomic-free aggregation. One warp per DST node, prefetch depth 2:
// gathers for edges t+1 and t+2 stay in flight while edge t's shuffle/exp
// chain executes; unroll-2 interleaves two independent reduction chains.
// ft[dst] held in registers (1 float4/lane). No atomics anywhere.
// Max-subtraction skipped: mathematically identical softmax; |p*scale| <~ 7.
// ---------------------------------------------------------------------------
__global__ void agg_kernel(float* __restrict__ out, int N) {
    const int node = (blockIdx.x * blockDim.x + threadIdx.x) >> 5;
    if (node >= N) return;
    const int lane = threadIdx.x & 31;

    const int start = g_off[node];
    const int deg   = g_cnt[node];

    const float4* ft4 = (const float4*)g_ft;
    const float4 b4 = ft4[(size_t)node * 32 + lane];

    float4 acc = make_float4(0.f, 0.f, 0.f, 0.f);
    float s = 0.0f;
    const float scale = 0.17677669529663687f;  // 1/sqrt(32)

    for (int base = 0; base < deg; base += 32) {
        int j = base + lane;
        int sj = (j < deg) ? g_csr_src[start + j] : 0;
        int cnt = min(32, deg - base);

        // prologue: two gathers in flight
        float4 a_t, a_t1;
        {
            int sn0 = __shfl_sync(0xffffffffu, sj, 0);
            a_t = ft4[(size_t)sn0 * 32 + lane];
        }
        if (cnt > 1) {
            int sn1 = __shfl_sync(0xffffffffu, sj, 1);
            a_t1 = ft4[(size_t)sn1 * 32 + lane];
        }

        #pragma unroll 2
        for (int t = 0; t < cnt; t++) {
            float4 cur = a_t;
            a_t = a_t1;
            if (t + 2 < cnt) {   // keep 2 gathers outstanding
                int sn = __shfl_sync(0xffffffffu, sj, t + 2);
                a_t1 = ft4[(size_t)sn * 32 + lane];
            }
            float p = cur.x * b4.x + cur.y * b4.y + cur.z * b4.z + cur.w * b4.w;
            p += __shfl_xor_sync(0xffffffffu, p, 4);
            p += __shfl_xor_sync(0xffffffffu, p, 2);
            p += __shfl_xor_sync(0xffffffffu, p, 1);
            float e = __expf(p * scale);
            s += e;
            acc.x += e * cur.x; acc.y += e * cur.y;
            acc.z += e * cur.z; acc.w += e * cur.w;
        }
    }

    float inv = (deg > 0) ? (1.0f / s) : 0.0f;
    float4 r = make_float4(acc.x * inv, acc.y * inv, acc.z * inv, acc.w * inv);
    ((float4*)out)[(size_t)node * 32 + lane] = r;
}

// ---------------------------------------------------------------------------
extern "C" void kernel_launch(void* const* d_in, const int* in_sizes, int n_in,
                              void* d_out, int out_size) {
    const float* feat = (const float*)d_in[0];
    const float* W    = (const float*)d_in[1];
    const int*   src  = (const int*)d_in[2];
    const int*   dst  = (const int*)d_in[3];
    float* out = (float*)d_out;

    const int N = in_sizes[0] / IN_FEATS;   // 50000
    const int E = in_sizes[2];              // 800000
    const int nb = (N + SCAN_B - 1) / SCAN_B;

    // One-time resources (stream/events/symbol addr) — resources only;
    // the captured work per call is identical every time.
    static cudaStream_t s_gemm = nullptr;
    static cudaEvent_t  ev_fork = nullptr, ev_join = nullptr;
    static int* cnt_ptr = nullptr;
    if (s_gemm == nullptr) {
        cudaStreamCreateWithFlags(&s_gemm, cudaStreamNonBlocking);
        cudaEventCreateWithFlags(&ev_fork, cudaEventDisableTiming);
        cudaEventCreateWithFlags(&ev_join, cudaEventDisableTiming);
        cudaGetSymbolAddress((void**)&cnt_ptr, g_cnt);
    }

    // ---- fork: GEMM branch issued FIRST (R8 order — measured best) ----
    cudaEventRecord(ev_fork, 0);
    cudaStreamWaitEvent(s_gemm, ev_fork, 0);
    gemm_kernel<<<(N + GM - 1) / GM, 256, 0, s_gemm>>>(feat, W, N);
    cudaEventRecord(ev_join, s_gemm);

    // ---- main stream: CSR build branch (depends only on src, dst) ----
    cudaMemsetAsync(cnt_ptr, 0, (size_t)N * sizeof(int));
    hist_kernel<<<(E + 255) / 256, 256>>>(dst, E);
    scan_phase1<<<nb, SCAN_B>>>(N);
    scan_phase3<<<nb, SCAN_B>>>(N);
    scatter_kernel<<<(E + 255) / 256, 256>>>(src, dst, E);

    // ---- join, then aggregate ----
    cudaStreamWaitEvent(0, ev_join, 0);
    {
        int warps_per_block = 8;  // 256 threads
        int blocks = (N + warps_per_block - 1) / warps_per_block;
        agg_kernel<<<blocks, 256>>>(out, N);
    }
}